// round 2
// baseline (speedup 1.0000x reference)
#include <cuda_runtime.h>
#include <math.h>

#define HIDDEN 1024
#define NINTER 256
#define WINDOW 64

// persistent scratch (allocation-free rule: __device__ globals)
__device__ float g_p[NINTER];
__device__ int   g_counter;   // reset to 0 by a memset node before each launch

// ---------------------------------------------------------------------------
// One fused kernel, grid = 256 blocks x 256 threads.
// Stage A: block b computes g_p[b] = tanh(fc1_w[b,:].h_t + fc1_b[b]) (fp64 acc,
//          same reduction order as the previously-passing kernel).
//          Grid-wide barrier via atomic counter + volatile spin (all 256
//          blocks are co-resident: 256 thr/block, ~40 regs -> >=4 blocks/SM).
// Stage B: every block redundantly computes p_t, window [ws,we], e_t
//          (g_p is in L2; read via __ldcg to bypass L1).
// Stage C: block b sums rows [ws,we] for columns 4b..4b+3; each thread does
//          <=3 independent predicated loads -> a single DRAM-latency batch.
// ---------------------------------------------------------------------------
__global__ void __launch_bounds__(256) fused_attn_kernel(
        const float* __restrict__ hs,
        const float* __restrict__ ht,
        const float* __restrict__ fc1_w,
        const float* __restrict__ fc1_b,
        const float* __restrict__ fc2_w,
        const float* __restrict__ fc2_b,
        float* __restrict__ out, int S) {
    const int tid  = threadIdx.x;
    const int bid  = blockIdx.x;
    const int lane = tid & 31;
    const int wid  = tid >> 5;

    __shared__ double sred[8];
    __shared__ float  colsum[256];
    __shared__ int    sh_ws, sh_we;
    __shared__ float  sh_et;

    // ---------------- Stage A: MLP layer 1, row = bid ----------------
    {
        float4 w = ((const float4*)(fc1_w + (size_t)bid * HIDDEN))[tid];
        float4 h = ((const float4*)ht)[tid];
        double acc = (double)w.x * h.x + (double)w.y * h.y
                   + (double)w.z * h.z + (double)w.w * h.w;
        #pragma unroll
        for (int o = 16; o > 0; o >>= 1)
            acc += __shfl_down_sync(0xffffffffu, acc, o);
        if (lane == 0) sred[wid] = acc;
        __syncthreads();
        if (tid == 0) {
            double z = 0.0;
            #pragma unroll
            for (int i = 0; i < 8; i++) z += sred[i];
            z += (double)fc1_b[bid];
            g_p[bid] = (float)tanh(z);
            __threadfence();
            atomicAdd(&g_counter, 1);
            // grid-wide spin: wait until all 256 rows are published
            while (*(volatile int*)&g_counter < NINTER) { }
            __threadfence();
        }
        __syncthreads();   // whole block released once tid0 passes the spin
    }

    // ---------------- Stage B: p_t / window / e_t (redundant per block) ----
    {
        double term = (double)__ldcg(&g_p[tid]) * (double)fc2_w[tid];
        #pragma unroll
        for (int o = 16; o > 0; o >>= 1)
            term += __shfl_down_sync(0xffffffffu, term, o);
        if (lane == 0) sred[wid] = term;
        __syncthreads();
        if (tid == 0) {
            double z = 0.0;
            #pragma unroll
            for (int i = 0; i < 8; i++) z += sred[i];
            z += (double)fc2_b[0];
            double pt = (double)S / (1.0 + exp(-z));
            double wsd = ceil(pt - (double)WINDOW);
            if (wsd < 0.0) wsd = 0.0;
            double wed = floor(pt + (double)WINDOW);
            if (wed > (double)(S - 1)) wed = (double)(S - 1);
            sh_ws = (int)wsd;
            sh_we = (int)wed;
            sh_et = (float)exp(((double)S - pt) / 2048.0);
        }
        __syncthreads();
    }

    // ---------------- Stage C: windowed row-sum, cols 4*bid .. 4*bid+3 -----
    {
        const int ws = sh_ws;
        const int we = sh_we;
        const int col    = (bid << 2) + (tid & 3);
        const int rowoff = tid >> 2;                 // 0..63
        const float* base = hs + col;

        const int r0 = ws + rowoff;                  // window <= 129 rows,
        float a = 0.f, b = 0.f, c = 0.f;             // 3 strided slots cover it
        if (r0       <= we) a = base[(size_t)(r0)       * HIDDEN];
        if (r0 + 64  <= we) b = base[(size_t)(r0 + 64)  * HIDDEN];
        if (r0 + 128 <= we) c = base[(size_t)(r0 + 128) * HIDDEN];
        colsum[tid] = (a + b) + c;
        __syncthreads();

        if (tid < 4) {
            float s = 0.f;
            #pragma unroll
            for (int i = 0; i < 64; i++) s += colsum[(i << 2) + tid];
            out[(bid << 2) + tid] = sh_et * s;
        }
    }
}

extern "C" void kernel_launch(void* const* d_in, const int* in_sizes, int n_in,
                              void* d_out, int out_size) {
    const float* hs    = (const float*)d_in[0];
    const float* ht    = (const float*)d_in[1];
    const float* fc1_w = (const float*)d_in[2];
    const float* fc1_b = (const float*)d_in[3];
    const float* fc2_w = (const float*)d_in[4];
    const float* fc2_b = (const float*)d_in[5];

    const int S = in_sizes[0] / HIDDEN;   // host-side constant, capture-safe

    // reset the grid-barrier counter each replay (memset node: graph-legal)
    void* ctr_addr = nullptr;
    cudaGetSymbolAddress(&ctr_addr, g_counter);
    cudaMemsetAsync(ctr_addr, 0, sizeof(int));

    fused_attn_kernel<<<NINTER, 256>>>(hs, ht, fc1_w, fc1_b, fc2_w, fc2_b,
                                       (float*)d_out, S);
}